// round 5
// baseline (speedup 1.0000x reference)
#include <cuda_runtime.h>

// Problem constants (shapes fixed by setup_inputs)
#define RESV 128
#define RES3 (RESV * RESV * RESV)     // 2,097,152
#define BB   4
#define CC   16
#define HH   256
#define WW   256
#define HW   (HH * WW)                // 65,536
#define FHW  (32 * 32)                // feature spatial size

// Scratch: per-(batch,axis) min of pc over valid pixels, stored as uint bits.
// pc >= 0 always (nocs>0, translation>=0, scale>=0), so IEEE float order
// == unsigned int order and atomicMin on bits is exact.
__device__ unsigned int g_lower[BB * 3];

// ---------------------------------------------------------------------------
// Kernel 1: zero the 512 MiB output grid with streaming float4 stores.
// ---------------------------------------------------------------------------
__global__ void zero_out_k(float4* __restrict__ out, int n4) {
    const float4 z = make_float4(0.f, 0.f, 0.f, 0.f);
    int stride = gridDim.x * blockDim.x;
    for (int i = blockIdx.x * blockDim.x + threadIdx.x; i < n4; i += stride)
        out[i] = z;
}

// ---------------------------------------------------------------------------
// Kernel 2: reset the min scratch to BIG (1e10, matching reference fill).
// ---------------------------------------------------------------------------
__global__ void init_lower_k() {
    if (threadIdx.x < BB * 3)
        g_lower[threadIdx.x] = __float_as_uint(1e10f);
}

// Validity test, matching reference: sigmoid(logit) > 0.75 AND all nocs > 0.
__device__ __forceinline__ bool pixel_valid(const float* __restrict__ nocs,
                                            const float* __restrict__ ml,
                                            int b, int pix,
                                            float& n0, float& n1, float& n2) {
    float m  = ml[b * HW + pix];
    n0 = nocs[((b * 3) + 0) * HW + pix];
    n1 = nocs[((b * 3) + 1) * HW + pix];
    n2 = nocs[((b * 3) + 2) * HW + pix];
    float sg = 1.0f / (1.0f + expf(-m));
    return (sg > 0.75f) & (n0 > 0.0f) & (n1 > 0.0f) & (n2 > 0.0f);
}

// pc = (nocs + translation) * scale, with EXACT rn add-then-mul, no FMA
// contraction possible (intrinsics are never fused by ptxas). Both the min
// reduction and the scatter must use this identical chain so a given pixel's
// pc is bit-identical in both kernels and to the reference's discrete ops.
__device__ __forceinline__ float pc_axis(float n, float t, float s) {
    return __fmul_rn(__fadd_rn(n, t), s);
}

// ---------------------------------------------------------------------------
// Kernel 3: per-(batch,axis) min of pc over valid pixels.
// 256 threads/block; HW divisible by 256 so each block maps to one batch.
// ---------------------------------------------------------------------------
__global__ void reduce_min_k(const float* __restrict__ nocs,
                             const float* __restrict__ ml,
                             const float* __restrict__ trans,
                             const float* __restrict__ scale) {
    int gid = blockIdx.x * blockDim.x + threadIdx.x;
    int b   = gid / HW;
    int pix = gid % HW;

    float n0, n1, n2;
    float v0 = 1e10f, v1 = 1e10f, v2 = 1e10f;
    if (pixel_valid(nocs, ml, b, pix, n0, n1, n2)) {
        float s = scale[b];
        v0 = pc_axis(n0, trans[b * 3 + 0], s);
        v1 = pc_axis(n1, trans[b * 3 + 1], s);
        v2 = pc_axis(n2, trans[b * 3 + 2], s);
    }
    #pragma unroll
    for (int off = 16; off; off >>= 1) {
        v0 = fminf(v0, __shfl_down_sync(0xFFFFFFFFu, v0, off));
        v1 = fminf(v1, __shfl_down_sync(0xFFFFFFFFu, v1, off));
        v2 = fminf(v2, __shfl_down_sync(0xFFFFFFFFu, v2, off));
    }
    __shared__ float s0[8], s1[8], s2[8];
    int warp = threadIdx.x >> 5;
    int lane = threadIdx.x & 31;
    if (lane == 0) { s0[warp] = v0; s1[warp] = v1; s2[warp] = v2; }
    __syncthreads();
    if (threadIdx.x == 0) {
        float m0 = s0[0], m1 = s1[0], m2 = s2[0];
        #pragma unroll
        for (int i = 1; i < 8; i++) {
            m0 = fminf(m0, s0[i]);
            m1 = fminf(m1, s1[i]);
            m2 = fminf(m2, s2[i]);
        }
        atomicMin(&g_lower[b * 3 + 0], __float_as_uint(m0));
        atomicMin(&g_lower[b * 3 + 1], __float_as_uint(m1));
        atomicMin(&g_lower[b * 3 + 2], __float_as_uint(m2));
    }
}

// ---------------------------------------------------------------------------
// Kernel 4: scatter-add upsampled features into the voxel grid.
// For a valid pixel: pc >= per-axis min so vox >= 0; composed index
// <= 255*16384 + 255*128 + 255 < 2^24, so int compose reproduces the
// reference's exact float32 compose + int cast + clip bit-for-bit.
// All pc math uses __f*_rn intrinsics: no FMA contraction, bit-identical to
// the reference's discrete add / mul / sub sequence.
// ---------------------------------------------------------------------------
__global__ void scatter_k(const float* __restrict__ nocs,
                          const float* __restrict__ ml,
                          const float* __restrict__ feat,
                          const float* __restrict__ trans,
                          const float* __restrict__ scale,
                          float* __restrict__ out) {
    int gid = blockIdx.x * blockDim.x + threadIdx.x;
    int b   = gid / HW;
    int pix = gid % HW;

    float n0, n1, n2;
    if (!pixel_valid(nocs, ml, b, pix, n0, n1, n2)) return;

    float s  = scale[b];
    float p0 = __fsub_rn(pc_axis(n0, trans[b * 3 + 0], s),
                         __uint_as_float(g_lower[b * 3 + 0]));
    float p1 = __fsub_rn(pc_axis(n1, trans[b * 3 + 1], s),
                         __uint_as_float(g_lower[b * 3 + 1]));
    float p2 = __fsub_rn(pc_axis(n2, trans[b * 3 + 2], s),
                         __uint_as_float(g_lower[b * 3 + 2]));

    // *128 is exact (power of two); floor exact.
    int vx = (int)floorf(__fmul_rn(p0, 128.0f));
    int vy = (int)floorf(__fmul_rn(p1, 128.0f));
    int vz = (int)floorf(__fmul_rn(p2, 128.0f));
    int idx = vx * (RESV * RESV) + vy * RESV + vz;
    idx = min(max(idx, 0), RES3 - 1);

    int h = pix / WW;
    int w = pix - h * WW;
    // nearest upsample 32x32 -> 256x256: source cell = (h/8, w/8)
    const float* fb = feat + (size_t)b * CC * FHW + (h >> 3) * 32 + (w >> 3);
    float*       ob = out  + (size_t)b * CC * RES3 + idx;

    #pragma unroll
    for (int c = 0; c < CC; c++) {
        atomicAdd(ob + (size_t)c * RES3, __ldg(fb + c * FHW));  // RED.global
    }
}

// ---------------------------------------------------------------------------
// Launch: all on the default stream, graph-capturable (kernels only).
// ---------------------------------------------------------------------------
extern "C" void kernel_launch(void* const* d_in, const int* in_sizes, int n_in,
                              void* d_out, int out_size) {
    const float* nocs  = (const float*)d_in[0];  // [4,3,256,256]
    const float* ml    = (const float*)d_in[1];  // [4,1,256,256]
    const float* feat  = (const float*)d_in[2];  // [4,16,32,32]
    const float* trans = (const float*)d_in[3];  // [4,3]
    const float* scale = (const float*)d_in[4];  // [4]
    float*       out   = (float*)d_out;          // [4,16,128,128,128]

    int n4 = out_size / 4;  // 33,554,432 float4s
    zero_out_k<<<8192, 256>>>((float4*)out, n4);
    init_lower_k<<<1, 32>>>();
    reduce_min_k<<<(BB * HW) / 256, 256>>>(nocs, ml, trans, scale);
    scatter_k<<<(BB * HW) / 256, 256>>>(nocs, ml, feat, trans, scale, out);
}

// round 6
// speedup vs baseline: 1.1029x; 1.1029x over previous
#include <cuda_runtime.h>

// Problem constants (shapes fixed by setup_inputs)
#define RESV 128
#define RES3 (RESV * RESV * RESV)     // 2,097,152
#define BB   4
#define CC   16
#define HH   256
#define WW   256
#define HW   (HH * WW)                // 65,536 pixels per batch
#define FHW  (32 * 32)                // feature spatial size

#define RB        32                  // reduction blocks (8 per batch)
#define SEG_PIX   (HW / 8)            // 8192 pixels per reduction block
#define ZB        8192                // zeroing blocks
#define F4_PER_BLK 4096               // float4s zeroed per block (64 KiB)

// Per-reduction-block partial mins (plain stores -> no init kernel needed).
__device__ float g_part[RB * 3];

// pc = (nocs + translation) * scale with exact rn add-then-mul; intrinsics
// are never FMA-contracted, so this is bit-identical to the reference's
// discrete add -> mul and identical between the reduce and scatter paths.
__device__ __forceinline__ float pc_axis(float n, float t, float s) {
    return __fmul_rn(__fadd_rn(n, t), s);
}

__device__ __forceinline__ bool valid_px(float m, float n0, float n1, float n2) {
    float sg = 1.0f / (1.0f + expf(-m));
    return (sg > 0.75f) & (n0 > 0.0f) & (n1 > 0.0f) & (n2 > 0.0f);
}

// ---------------------------------------------------------------------------
// Kernel A: fused zero-fill + min-reduction.
//   blocks [0, RB):       per-segment min of pc over valid pixels -> g_part
//   blocks [RB, RB+ZB):   zero the 512 MiB output grid (streaming stores)
// The reduction blocks (4 MB of reads) hide entirely under the zero-fill.
// ---------------------------------------------------------------------------
__global__ void fused_zero_reduce_k(const float* __restrict__ nocs,
                                    const float* __restrict__ ml,
                                    const float* __restrict__ trans,
                                    const float* __restrict__ scale,
                                    float4* __restrict__ out) {
    if (blockIdx.x >= RB) {
        // ------------- zero-fill path -------------
        int zb = blockIdx.x - RB;
        float4* p = out + (size_t)zb * F4_PER_BLK + threadIdx.x;
        const float4 z = make_float4(0.f, 0.f, 0.f, 0.f);
        #pragma unroll
        for (int i = 0; i < F4_PER_BLK / 256; i++)
            __stcs(p + i * 256, z);
        return;
    }

    // ------------- reduction path -------------
    int rb  = blockIdx.x;
    int b   = rb >> 3;
    int seg = rb & 7;
    int base = b * HW + seg * SEG_PIX;           // multiple of 4 -> float4 ok

    const float4* m4 = (const float4*)(ml   + base);
    const float4* x4 = (const float4*)(nocs + (b * 3 + 0) * HW + seg * SEG_PIX);
    const float4* y4 = (const float4*)(nocs + (b * 3 + 1) * HW + seg * SEG_PIX);
    const float4* z4 = (const float4*)(nocs + (b * 3 + 2) * HW + seg * SEG_PIX);

    float t0 = trans[b * 3 + 0], t1 = trans[b * 3 + 1], t2 = trans[b * 3 + 2];
    float s  = scale[b];

    float v0 = 1e10f, v1 = 1e10f, v2 = 1e10f;
    #pragma unroll
    for (int i = 0; i < SEG_PIX / 4 / 256; i++) {   // 8 iterations
        int j = threadIdx.x + i * 256;
        float4 m = m4[j], a = x4[j], c = y4[j], d = z4[j];
        const float* mp = &m.x; const float* ap = &a.x;
        const float* cp = &c.x; const float* dp = &d.x;
        #pragma unroll
        for (int k = 0; k < 4; k++) {
            if (valid_px(mp[k], ap[k], cp[k], dp[k])) {
                v0 = fminf(v0, pc_axis(ap[k], t0, s));
                v1 = fminf(v1, pc_axis(cp[k], t1, s));
                v2 = fminf(v2, pc_axis(dp[k], t2, s));
            }
        }
    }
    #pragma unroll
    for (int off = 16; off; off >>= 1) {
        v0 = fminf(v0, __shfl_down_sync(0xFFFFFFFFu, v0, off));
        v1 = fminf(v1, __shfl_down_sync(0xFFFFFFFFu, v1, off));
        v2 = fminf(v2, __shfl_down_sync(0xFFFFFFFFu, v2, off));
    }
    __shared__ float s0[8], s1[8], s2[8];
    int warp = threadIdx.x >> 5, lane = threadIdx.x & 31;
    if (lane == 0) { s0[warp] = v0; s1[warp] = v1; s2[warp] = v2; }
    __syncthreads();
    if (threadIdx.x == 0) {
        float m0 = s0[0], m1 = s1[0], m2 = s2[0];
        #pragma unroll
        for (int i = 1; i < 8; i++) {
            m0 = fminf(m0, s0[i]);
            m1 = fminf(m1, s1[i]);
            m2 = fminf(m2, s2[i]);
        }
        g_part[rb * 3 + 0] = m0;
        g_part[rb * 3 + 1] = m1;
        g_part[rb * 3 + 2] = m2;
    }
}

// ---------------------------------------------------------------------------
// Kernel B: scatter-add. 4 pixels per thread (float4 loads); the 4 pixels
// (w aligned to 4) always share one nearest-neighbor feature cell, so the 16
// channel values are loaded once per thread. Index math: vox >= 0 (pc >= min)
// and composed idx < 2^24, so int compose == reference float compose exactly.
// ---------------------------------------------------------------------------
__global__ void scatter_k(const float* __restrict__ nocs,
                          const float* __restrict__ ml,
                          const float* __restrict__ feat,
                          const float* __restrict__ trans,
                          const float* __restrict__ scale,
                          float* __restrict__ out) {
    int gid4 = blockIdx.x * blockDim.x + threadIdx.x;   // 0 .. B*HW/4
    int b    = gid4 >> 14;                              // 16384 groups/batch
    int pix  = (gid4 & 16383) * 4;

    // block-local lower = min over this batch's 8 partials (all threads in a
    // block share one batch: 256 | 16384)
    __shared__ float lower[3];
    if (threadIdx.x < 3) {
        float m = 1e10f;
        #pragma unroll
        for (int j = 0; j < 8; j++)
            m = fminf(m, g_part[(b * 8 + j) * 3 + threadIdx.x]);
        lower[threadIdx.x] = m;
    }
    __syncthreads();

    int base = b * HW + pix;
    float4 m4 = *(const float4*)(ml + base);
    float4 a4 = *(const float4*)(nocs + (b * 3 + 0) * HW + pix);
    float4 c4 = *(const float4*)(nocs + (b * 3 + 1) * HW + pix);
    float4 d4 = *(const float4*)(nocs + (b * 3 + 2) * HW + pix);
    const float* mp = &m4.x; const float* ap = &a4.x;
    const float* cp = &c4.x; const float* dp = &d4.x;

    bool v[4];
    bool any = false;
    #pragma unroll
    for (int k = 0; k < 4; k++) {
        v[k] = valid_px(mp[k], ap[k], cp[k], dp[k]);
        any |= v[k];
    }
    if (!any) return;

    float t0 = trans[b * 3 + 0], t1 = trans[b * 3 + 1], t2 = trans[b * 3 + 2];
    float s  = scale[b];
    float l0 = lower[0], l1 = lower[1], l2 = lower[2];

    // one feature cell serves all 4 pixels: h identical, w..w+3 within one oct
    int h = pix >> 8;
    int w = pix & 255;
    const float* fb = feat + (size_t)b * CC * FHW + (h >> 3) * 32 + (w >> 3);
    float f[CC];
    #pragma unroll
    for (int c = 0; c < CC; c++) f[c] = __ldg(fb + c * FHW);

    float* ob = out + (size_t)b * CC * RES3;

    #pragma unroll
    for (int k = 0; k < 4; k++) {
        if (!v[k]) continue;
        float p0 = __fsub_rn(pc_axis(ap[k], t0, s), l0);
        float p1 = __fsub_rn(pc_axis(cp[k], t1, s), l1);
        float p2 = __fsub_rn(pc_axis(dp[k], t2, s), l2);
        int vx = (int)floorf(__fmul_rn(p0, 128.0f));
        int vy = (int)floorf(__fmul_rn(p1, 128.0f));
        int vz = (int)floorf(__fmul_rn(p2, 128.0f));
        int idx = vx * (RESV * RESV) + vy * RESV + vz;
        idx = min(max(idx, 0), RES3 - 1);
        #pragma unroll
        for (int c = 0; c < CC; c++)
            atomicAdd(ob + (size_t)c * RES3 + idx, f[c]);   // RED.global
    }
}

// ---------------------------------------------------------------------------
// Launch: two kernels, default stream, graph-capturable.
// ---------------------------------------------------------------------------
extern "C" void kernel_launch(void* const* d_in, const int* in_sizes, int n_in,
                              void* d_out, int out_size) {
    const float* nocs  = (const float*)d_in[0];  // [4,3,256,256]
    const float* ml    = (const float*)d_in[1];  // [4,1,256,256]
    const float* feat  = (const float*)d_in[2];  // [4,16,32,32]
    const float* trans = (const float*)d_in[3];  // [4,3]
    const float* scale = (const float*)d_in[4];  // [4]
    float*       out   = (float*)d_out;          // [4,16,128,128,128]

    fused_zero_reduce_k<<<RB + ZB, 256>>>(nocs, ml, trans, scale, (float4*)out);
    scatter_k<<<(BB * HW / 4) / 256, 256>>>(nocs, ml, feat, trans, scale, out);
}